// round 16
// baseline (speedup 1.0000x reference)
#include <cuda_runtime.h>
#include <math.h>

#define NP 131072   // 64*64*32 voxels
#define CH 96

// ---- scratch (static device arrays; no allocation allowed) ----
__device__ float  d_h [CH*NP];          // [c][x][y][z]
__device__ float  d_x2[CH*NP];          // skip-conv output
__device__ float2 d_S2[CH*64*16*8];     // after z+y DFT [c][x][ky][kz]
__device__ float2 d_S3[CH*16*16*8];     // after x-DFT   [c][kx][ky][kz]
__device__ float2 d_G [CH*16*16*8];     // mode-mixed    [o][kx][ky][kz]
__device__ float2 d_T2[CH*64*16*8];     // inv x         [o][x][ky][kz]
__device__ float2 d_tw[64];             // e^{-2pi i r/64}

__global__ void k_tw() {
    int t = threadIdx.x;
    float s, c;
    sincospif(t * (2.0f / 64.0f), &s, &c);
    d_tw[t] = make_float2(c, -s);       // e^{-2*pi*i*t/64}
}

// ---- tf32 helpers ----
__device__ __forceinline__ unsigned f2tf(float f) {
    unsigned r;
    asm("cvt.rna.tf32.f32 %0, %1;" : "=r"(r) : "f"(f));
    return r;
}
__device__ __forceinline__ void mma_tf32(float* c, const unsigned* a, const unsigned* b) {
    asm("mma.sync.aligned.m16n8k8.row.col.f32.tf32.tf32.f32 "
        "{%0,%1,%2,%3}, {%4,%5,%6,%7}, {%8,%9}, {%0,%1,%2,%3};"
        : "+f"(c[0]), "+f"(c[1]), "+f"(c[2]), "+f"(c[3])
        : "r"(a[0]), "r"(a[1]), "r"(a[2]), "r"(a[3]), "r"(b[0]), "r"(b[1]));
}
__device__ __forceinline__ float2 cmul(float2 a, float2 b) {
    return make_float2(a.x * b.x - a.y * b.y, a.x * b.y + a.y * b.x);
}

// ---- fc0: [p][nt][nvar] + grid -> h[c][p] ----
__global__ void k_fc0(const float* __restrict__ x, const float* __restrict__ w,
                      const float* __restrict__ b, float* __restrict__ h) {
    __shared__ float vsh[64 * 29];
    __shared__ float wsh[28 * 96];
    __shared__ float bsh[96];
    int t = threadIdx.x;                 // 256
    int p0 = blockIdx.x * 64;
    for (int idx = t; idx < 64 * 25; idx += 256) {
        int p = idx / 25, j = idx % 25;
        int nv = j / 5, nt = j % 5;      // v[nv*5+nt] = x[p,nt,nv]
        vsh[p * 29 + j] = x[(p0 + p) * 25 + nt * 5 + nv];
    }
    if (t < 192) {
        int p = t % 64, j = t / 64;
        int pg = p0 + p;
        float g;
        if (j == 0)      g = (float)(pg >> 11)        * (1.0f / 63.0f);
        else if (j == 1) g = (float)((pg >> 5) & 63)  * (1.0f / 63.0f);
        else             g = (float)(pg & 31)         * (1.0f / 31.0f);
        vsh[p * 29 + 25 + j] = g;
    }
    for (int idx = t; idx < 28 * 96; idx += 256) wsh[idx] = w[idx];
    if (t < 96) bsh[t] = b[t];
    __syncthreads();
    int p = t & 63;
    for (int c = t >> 6; c < 96; c += 4) {
        float acc = bsh[c];
        #pragma unroll
        for (int j = 0; j < 28; j++) acc = fmaf(vsh[p * 29 + j], wsh[j * 96 + c], acc);
        h[c * NP + p0 + p] = acc;
    }
}

// ---- fused forward z-DFT + y-DFT: h[c][x][y][z] -> S2[c][x][ky<16][kz<8] ----
// Block = 2 cx. Phase1: 4 kz/thread, radix-2 z-fold, broadcast float4 twiddle table.
// Phase2: radix-2 y-fold + 4 ky/thread + twiddle recurrence + shfl reduce.
__global__ void __launch_bounds__(256, 5)
k_fwdZY(const float* __restrict__ h, float2* __restrict__ S2) {
    __shared__ float  sh[2 * 64 * 33];   // [cxi][y][z] padded
    __shared__ float2 s1[2 * 64 * 9];    // [cxi][y][kz] padded
    __shared__ float2 tws[64];
    __shared__ float2 ttab[128];         // [grp][z][kzi]: tw for kz = grp+2*kzi
    int t = threadIdx.x;                 // 256
    const float4* row4 = (const float4*)(h + (long)blockIdx.x * 4096);
    #pragma unroll
    for (int fi = t; fi < 1024; fi += 256) {
        float4 v = row4[fi];
        int cxi = fi >> 9, rem = fi & 511;
        int y = rem >> 3, z = (rem & 7) * 4;
        float* dst = sh + cxi * 2112 + y * 33 + z;
        dst[0] = v.x; dst[1] = v.y; dst[2] = v.z; dst[3] = v.w;
    }
    if (t < 64) tws[t] = d_tw[t];
    if (t >= 64 && t < 192) {
        int e = t - 64;                  // grp = e>>6, z = (e>>2)&15, kzi = e&3
        int grp = e >> 6, z = (e >> 2) & 15, kzi = e & 3;
        ttab[e] = d_tw[(2 * (grp + 2 * kzi) * z) & 63];
    }
    __syncthreads();
    // phase 1: z-DFT. thread = (cxi, grp, y): kz = {grp, grp+2, grp+4, grp+6}
    {
        int cxi = t >> 7, u = t & 127;
        int grp = u >> 6, y = u & 63;
        float sgn = grp ? -1.f : 1.f;    // (-1)^kz, kz parity = grp
        const float* shy = sh + cxi * 2112 + y * 33;
        const float4* tt = (const float4*)(ttab + grp * 64);
        float r0 = 0.f, i0 = 0.f, r1 = 0.f, i1 = 0.f;
        float r2 = 0.f, i2 = 0.f, r3 = 0.f, i3 = 0.f;
        #pragma unroll
        for (int z = 0; z < 16; z++) {
            float s = fmaf(sgn, shy[z + 16], shy[z]);
            float4 wa = tt[z * 2 + 0];   // kz = grp, grp+2
            float4 wb = tt[z * 2 + 1];   // kz = grp+4, grp+6
            r0 = fmaf(s, wa.x, r0); i0 = fmaf(s, wa.y, i0);
            r1 = fmaf(s, wa.z, r1); i1 = fmaf(s, wa.w, i1);
            r2 = fmaf(s, wb.x, r2); i2 = fmaf(s, wb.y, i2);
            r3 = fmaf(s, wb.z, r3); i3 = fmaf(s, wb.w, i3);
        }
        float2* s1y = s1 + cxi * 576 + y * 9;
        s1y[grp + 0] = make_float2(r0, i0);
        s1y[grp + 2] = make_float2(r1, i1);
        s1y[grp + 4] = make_float2(r2, i2);
        s1y[grp + 6] = make_float2(r3, i3);
    }
    __syncthreads();
    // phase 2: y-DFT. thread = (yq=t&3, kyg=(t>>2)&3, kz=(t>>4)&7, cxi=t>>7)
    {
        int yq = t & 3, kyg = (t >> 2) & 3, kz = (t >> 4) & 7, cxi = t >> 7;
        float sgn2 = (kyg & 1) ? -1.f : 1.f;   // (-1)^kye
        int kye0 = kyg, kye1 = kyg + 4, kye2 = kyg + 56, kye3 = kyg + 60;
        int y0 = yq * 8;
        float2 tw0 = tws[(kye0 * y0) & 63], st0 = tws[kye0];
        float2 tw1 = tws[(kye1 * y0) & 63], st1 = tws[kye1];
        float2 tw2 = tws[(kye2 * y0) & 63], st2 = tws[kye2];
        float2 tw3 = tws[(kye3 * y0) & 63], st3 = tws[kye3];
        float2 a0 = make_float2(0.f, 0.f), a1 = a0, a2 = a0, a3 = a0;
        const float2* s1c = s1 + cxi * 576;
        #pragma unroll
        for (int i = 0; i < 8; i++) {
            int y = y0 + i;
            float2 va = s1c[y * 9 + kz];
            float2 vb = s1c[(y + 32) * 9 + kz];
            float2 fs = make_float2(fmaf(sgn2, vb.x, va.x), fmaf(sgn2, vb.y, va.y));
            a0.x += fs.x * tw0.x - fs.y * tw0.y; a0.y += fs.x * tw0.y + fs.y * tw0.x;
            a1.x += fs.x * tw1.x - fs.y * tw1.y; a1.y += fs.x * tw1.y + fs.y * tw1.x;
            a2.x += fs.x * tw2.x - fs.y * tw2.y; a2.y += fs.x * tw2.y + fs.y * tw2.x;
            a3.x += fs.x * tw3.x - fs.y * tw3.y; a3.y += fs.x * tw3.y + fs.y * tw3.x;
            tw0 = cmul(tw0, st0); tw1 = cmul(tw1, st1);
            tw2 = cmul(tw2, st2); tw3 = cmul(tw3, st3);
        }
        #pragma unroll
        for (int m = 1; m <= 2; m <<= 1) {
            a0.x += __shfl_xor_sync(0xffffffffu, a0.x, m);
            a0.y += __shfl_xor_sync(0xffffffffu, a0.y, m);
            a1.x += __shfl_xor_sync(0xffffffffu, a1.x, m);
            a1.y += __shfl_xor_sync(0xffffffffu, a1.y, m);
            a2.x += __shfl_xor_sync(0xffffffffu, a2.x, m);
            a2.y += __shfl_xor_sync(0xffffffffu, a2.y, m);
            a3.x += __shfl_xor_sync(0xffffffffu, a3.x, m);
            a3.y += __shfl_xor_sync(0xffffffffu, a3.y, m);
        }
        if (yq == 0) {
            long cx = (long)blockIdx.x * 2 + cxi;
            float2* out = S2 + cx * 128;
            out[(kyg + 0)  * 8 + kz] = a0;
            out[(kyg + 4)  * 8 + kz] = a1;
            out[(kyg + 8)  * 8 + kz] = a2;
            out[(kyg + 12) * 8 + kz] = a3;
        }
    }
}

// ---- forward x-DFT (16 kept kx); block = (c, ky), contiguous 64B accesses ----
__global__ void k_fwdX(const float2* __restrict__ S2, float2* __restrict__ S3) {
    __shared__ float2 sh[64 * 8];        // [x][kz]
    __shared__ float2 tws[64];
    int t = threadIdx.x;                 // 128
    int c = blockIdx.x >> 4, ky = blockIdx.x & 15;
    const float2* base = S2 + ((long)c * 1024 + ky) * 8;   // + x*128 + kz
    #pragma unroll
    for (int idx = t; idx < 512; idx += 128) {
        int x = idx >> 3, kz = idx & 7;
        sh[idx] = base[x * 128 + kz];
    }
    if (t < 64) tws[t] = d_tw[t];
    __syncthreads();
    int kx = t >> 3, kz = t & 7;
    int kxe = (kx < 8) ? kx : kx + 48;
    float re = 0.f, im = 0.f;
    #pragma unroll
    for (int x = 0; x < 64; x++) {
        float2 v = sh[x * 8 + kz];
        float2 w = tws[(kxe * x) & 63];
        re += v.x * w.x - v.y * w.y;
        im += v.x * w.y + v.y * w.x;
    }
    S3[(((long)c * 16 + kx) * 16 + ky) * 8 + kz] = make_float2(re, im);
}

// ---- mode mix: zero-smem, zero-barrier streaming version ----
// block = (corner, o, m-half): 768 x 128 thr. Per i: one float4 of S3 (L2)
// + one float4 of w_spec (DRAM stream). Accumulation order identical to R15.
__global__ void __launch_bounds__(128)
k_mix(const float2* __restrict__ S3, const float* __restrict__ wspec,
      float2* __restrict__ G) {
    int t = threadIdx.x;                 // 128
    int bid = blockIdx.x;
    int mh = bid & 1;
    int o = (bid >> 1) % 96;
    int corner = (bid >> 1) / 96;
    int kx0 = (corner & 1) * 8, ky0 = (corner >> 1) * 8;
    int gm0 = mh * 256 + 2 * t;          // even -> float4-aligned S3 pair
    int a = gm0 >> 6, rem = gm0 & 63;
    const float4* S34 = (const float4*)S3;
    long sbase = ((long)(kx0 + a) * 64) + ky0 * 4 + (rem >> 1);   // float4 units
    const float4* w4 = (const float4*)wspec;
    long wbase = (((long)corner * 96) * 96 + o) * 256 + mh * 128 + t;
    float2 acc0 = make_float2(0.f, 0.f), acc1 = make_float2(0.f, 0.f);
    #pragma unroll 4
    for (int i = 0; i < 96; i++) {
        float4 s = __ldg(&S34[sbase + (long)i * 1024]);           // (m0.re,m0.im,m1.re,m1.im)
        float4 w = __ldcs(&w4[wbase + (long)i * 24576]);          // 96*256 float4 per i
        acc0.x += s.x * w.x - s.y * w.y;
        acc0.y += s.x * w.y + s.y * w.x;
        acc1.x += s.z * w.z - s.w * w.w;
        acc1.y += s.z * w.w + s.w * w.z;
    }
    int bb = (gm0 >> 3) & 7, kzz = gm0 & 7;
    float4* G4 = (float4*)G;
    G4[(((long)o * 16 + kx0 + a) * 16 + ky0 + bb) * 4 + (kzz >> 1)] =
        make_float4(acc0.x, acc0.y, acc1.x, acc1.y);
}

// ---- inverse x (e^{+i}); block = (o, ky), contiguous 64B accesses ----
__global__ void k_invX(const float2* __restrict__ G, float2* __restrict__ T2) {
    __shared__ float2 gsh[128];          // [kx][kz]
    __shared__ float2 tws[64];
    int t = threadIdx.x;                 // 256
    int o = blockIdx.x >> 4, ky = blockIdx.x & 15;
    if (t < 128) {
        int kx = t >> 3, kz = t & 7;
        gsh[t] = G[(long)o * 2048 + kx * 128 + ky * 8 + kz];
    }
    if (t >= 128 && t < 192) tws[t - 128] = d_tw[t - 128];
    __syncthreads();
    int kz = t & 7, x0 = t >> 3;         // x0 0..31
    #pragma unroll
    for (int pp = 0; pp < 2; pp++) {
        int x = x0 + 32 * pp;
        float re = 0.f, im = 0.f;
        #pragma unroll
        for (int kx = 0; kx < 16; kx++) {
            int kxe = (kx < 8) ? kx : kx + 48;
            float2 v = gsh[kx * 8 + kz];
            float2 w = tws[(kxe * x) & 63];     // conj -> e^{+i}
            re += v.x * w.x + v.y * w.y;
            im += v.y * w.x - v.x * w.y;
        }
        T2[(((long)o * 64 + x) * 16 + ky) * 8 + kz] = make_float2(re, im);
    }
}

// ---- skip 1x1 conv via tf32 warp-MMA: x2[o][p] = sum_i W[o][i] h[i][p] + b[o]
// block: 192 threads (6 warps), tile 96o x 128p, K=96 (12 ksteps)
__global__ void k_skip(const float* __restrict__ h, const float* __restrict__ W,
                       const float* __restrict__ b, float* __restrict__ x2) {
    __shared__ unsigned hsh[96 * 128];   // tf32 bits, idx(i,p) = i*128 + (p ^ ((i&3)<<3))
    int t = threadIdx.x;
    int warp = t >> 5, lane = t & 31;
    int q = lane >> 2, r = lane & 3;
    int p0 = blockIdx.x * 128;
    for (int idx = t; idx < 96 * 32; idx += 192) {
        int i = idx >> 5, p = (idx & 31) * 4;
        float4 v = *(const float4*)(h + (long)i * NP + p0 + p);
        int sp = p ^ ((i & 3) << 3);
        uint4 u = make_uint4(f2tf(v.x), f2tf(v.y), f2tf(v.z), f2tf(v.w));
        *(uint4*)(hsh + i * 128 + sp) = u;
    }
    int o0 = warp * 16;
    unsigned A[12][4];
    #pragma unroll
    for (int ks = 0; ks < 12; ks++) {
        A[ks][0] = f2tf(__ldg(&W[(o0 + q) * 96 + ks * 8 + r]));
        A[ks][1] = f2tf(__ldg(&W[(o0 + q + 8) * 96 + ks * 8 + r]));
        A[ks][2] = f2tf(__ldg(&W[(o0 + q) * 96 + ks * 8 + r + 4]));
        A[ks][3] = f2tf(__ldg(&W[(o0 + q + 8) * 96 + ks * 8 + r + 4]));
    }
    float acc[16][4];
    #pragma unroll
    for (int nt = 0; nt < 16; nt++)
        #pragma unroll
        for (int k = 0; k < 4; k++) acc[nt][k] = 0.f;
    __syncthreads();
    #pragma unroll
    for (int ks = 0; ks < 12; ks++) {
        #pragma unroll
        for (int nt = 0; nt < 16; nt++) {
            unsigned bf[2];
            int col = (nt * 8 + q) ^ (r << 3);
            bf[0] = hsh[(ks * 8 + r) * 128 + col];
            bf[1] = hsh[(ks * 8 + r + 4) * 128 + col];
            mma_tf32(acc[nt], A[ks], bf);
        }
    }
    float bv0 = __ldg(&b[o0 + q]);
    float bv8 = __ldg(&b[o0 + q + 8]);
    #pragma unroll
    for (int nt = 0; nt < 16; nt++) {
        int p = p0 + nt * 8 + 2 * r;
        *(float2*)(x2 + (long)(o0 + q) * NP + p)     = make_float2(acc[nt][0] + bv0, acc[nt][1] + bv0);
        *(float2*)(x2 + (long)(o0 + q + 8) * NP + p) = make_float2(acc[nt][2] + bv8, acc[nt][3] + bv8);
    }
}

// ---- fused inverse y + inverse z + skip add + (gelu): writes h in place ----
// Phase2 uses z-symmetry: term(z+16) = (-1)^kz term(z) -> 2 outputs/product,
// and t1s reads become warp-broadcast (16 lanes share one y).
__global__ void __launch_bounds__(256, 5)
k_invYZ(const float2* __restrict__ T2, const float* __restrict__ x2,
        float* __restrict__ h, int do_gelu) {
    __shared__ float2 t2s[128];          // [ky][kz]
    __shared__ float2 t1s[64 * 9];       // [y][kz] padded
    __shared__ float2 tws[64];
    int t = threadIdx.x;                 // 256
    int ox = blockIdx.x;
    if (t < 128) t2s[t] = T2[(long)ox * 128 + t];
    if (t >= 128 && t < 192) tws[t - 128] = d_tw[t - 128];
    __syncthreads();
    // phase 1: inverse y with twiddle recurrence + y-sign trick.
    {
        int kz = t & 7, yq = t >> 3;     // yq 0..31
        float2 step = tws[yq];           // w(yq)
        float2 tw = make_float2(1.f, 0.f);
        float r1 = 0.f, i1 = 0.f, r2 = 0.f, i2 = 0.f;
        #pragma unroll
        for (int ky = 0; ky < 16; ky++) {
            if (ky == 8) tw = tws[(56 * yq) & 63];   // kye jumps 7 -> 56
            float2 v = t2s[ky * 8 + kz];
            float tr = v.x * tw.x + v.y * tw.y;      // Re(v e^{+i})
            float ti = v.y * tw.x - v.x * tw.y;
            r1 += tr; i1 += ti;
            if (ky & 1) { r2 -= tr; i2 -= ti; }
            else        { r2 += tr; i2 += ti; }
            tw = cmul(tw, step);
        }
        float sc = (kz == 0) ? (1.0f / 131072.0f) : (2.0f / 131072.0f);
        t1s[yq * 9 + kz] = make_float2(r1 * sc, i1 * sc);
        t1s[(yq + 32) * 9 + kz] = make_float2(r2 * sc, i2 * sc);
    }
    __syncthreads();
    // phase 2: inverse z (real part) + skip + gelu; z-symmetry pair (z0, z0+16)
    int z0 = t & 15, yg = t >> 4;        // yg 0..15
    float2 tzs[8];
    {
        float2 st = tws[(2 * z0) & 63];
        tzs[0] = make_float2(1.f, 0.f);
        tzs[1] = st;
        #pragma unroll
        for (int k = 2; k < 8; k++) tzs[k] = cmul(tzs[k - 1], st);
    }
    const float* x2row = x2 + (long)ox * 2048;
    float* hrow = h + (long)ox * 2048;
    #pragma unroll
    for (int pass = 0; pass < 4; pass++) {
        int y = yg + 16 * pass;
        float a = 0.f, bq = 0.f;
        #pragma unroll
        for (int kz = 0; kz < 8; kz++) {
            float2 v = t1s[y * 9 + kz];
            float term = v.x * tzs[kz].x + v.y * tzs[kz].y;  // Re(v e^{+i th})
            a += term;
            if (kz & 1) bq -= term; else bq += term;
        }
        float r1 = a  + x2row[y * 32 + z0];
        float r2 = bq + x2row[y * 32 + z0 + 16];
        if (do_gelu) {
            r1 = 0.5f * r1 * (1.0f + erff(r1 * 0.70710678118f));
            r2 = 0.5f * r2 * (1.0f + erff(r2 * 0.70710678118f));
        }
        hrow[y * 32 + z0]      = r1;
        hrow[y * 32 + z0 + 16] = r2;
    }
}

// ---- fused head: out = gelu(h @ fc1 + b1) @ fc2 + b2 (no d_g round-trip)
// block: 256 threads (8 warps), tile 128j x 128p, K=96; g tile in dynamic smem.
__global__ void k_fc12(const float* __restrict__ h, const float* __restrict__ w1,
                       const float* __restrict__ b1, const float* __restrict__ w2,
                       const float* __restrict__ b2, float* __restrict__ out) {
    __shared__ unsigned hsh[96 * 128];   // tf32 bits, idx(i,p) = i*128 + (p ^ ((i&3)<<3))
    __shared__ float w2s[128 * 5];
    __shared__ float part[2 * 5 * 128];  // fc2 partials [half][v][p]
    extern __shared__ float gsh[];       // [j][p] stride 130 -> 66560 B
    int t = threadIdx.x;
    int warp = t >> 5, lane = t & 31;
    int q = lane >> 2, r = lane & 3;
    int p0 = blockIdx.x * 128;
    for (int idx = t; idx < 96 * 32; idx += 256) {
        int i = idx >> 5, p = (idx & 31) * 4;
        float4 v = *(const float4*)(h + (long)i * NP + p0 + p);
        int sp = p ^ ((i & 3) << 3);
        uint4 u = make_uint4(f2tf(v.x), f2tf(v.y), f2tf(v.z), f2tf(v.w));
        *(uint4*)(hsh + i * 128 + sp) = u;
    }
    for (int idx = t; idx < 640; idx += 256) w2s[idx] = w2[idx];
    int j0 = warp * 16;
    unsigned A[12][4];
    #pragma unroll
    for (int ks = 0; ks < 12; ks++) {
        A[ks][0] = f2tf(__ldg(&w1[(ks * 8 + r) * 128 + j0 + q]));
        A[ks][1] = f2tf(__ldg(&w1[(ks * 8 + r) * 128 + j0 + q + 8]));
        A[ks][2] = f2tf(__ldg(&w1[(ks * 8 + r + 4) * 128 + j0 + q]));
        A[ks][3] = f2tf(__ldg(&w1[(ks * 8 + r + 4) * 128 + j0 + q + 8]));
    }
    float acc[16][4];
    #pragma unroll
    for (int nt = 0; nt < 16; nt++)
        #pragma unroll
        for (int k = 0; k < 4; k++) acc[nt][k] = 0.f;
    __syncthreads();
    #pragma unroll
    for (int ks = 0; ks < 12; ks++) {
        #pragma unroll
        for (int nt = 0; nt < 16; nt++) {
            unsigned bf[2];
            int col = (nt * 8 + q) ^ (r << 3);
            bf[0] = hsh[(ks * 8 + r) * 128 + col];
            bf[1] = hsh[(ks * 8 + r + 4) * 128 + col];
            mma_tf32(acc[nt], A[ks], bf);
        }
    }
    float bj0 = __ldg(&b1[j0 + q]);
    float bj8 = __ldg(&b1[j0 + q + 8]);
    #pragma unroll
    for (int nt = 0; nt < 16; nt++) {
        int p = nt * 8 + 2 * r;
        float s0 = acc[nt][0] + bj0, s1 = acc[nt][1] + bj0;
        float s2 = acc[nt][2] + bj8, s3 = acc[nt][3] + bj8;
        s0 = 0.5f * s0 * (1.0f + erff(s0 * 0.70710678118f));
        s1 = 0.5f * s1 * (1.0f + erff(s1 * 0.70710678118f));
        s2 = 0.5f * s2 * (1.0f + erff(s2 * 0.70710678118f));
        s3 = 0.5f * s3 * (1.0f + erff(s3 * 0.70710678118f));
        *(float2*)(gsh + (j0 + q) * 130 + p)     = make_float2(s0, s1);
        *(float2*)(gsh + (j0 + q + 8) * 130 + p) = make_float2(s2, s3);
    }
    __syncthreads();
    // fc2 stage: thread = (p = t&127, half = t>>7); 64 j each
    {
        int p = t & 127, half = t >> 7;
        float a0 = 0.f, a1 = 0.f, a2 = 0.f, a3 = 0.f, a4 = 0.f;
        int jb = half * 64;
        #pragma unroll 4
        for (int j = jb; j < jb + 64; j++) {
            float gv = gsh[j * 130 + p];
            a0 = fmaf(gv, w2s[j * 5 + 0], a0);
            a1 = fmaf(gv, w2s[j * 5 + 1], a1);
            a2 = fmaf(gv, w2s[j * 5 + 2], a2);
            a3 = fmaf(gv, w2s[j * 5 + 3], a3);
            a4 = fmaf(gv, w2s[j * 5 + 4], a4);
        }
        part[(half * 5 + 0) * 128 + p] = a0;
        part[(half * 5 + 1) * 128 + p] = a1;
        part[(half * 5 + 2) * 128 + p] = a2;
        part[(half * 5 + 3) * 128 + p] = a3;
        part[(half * 5 + 4) * 128 + p] = a4;
    }
    __syncthreads();
    for (int idx = t; idx < 640; idx += 256) {
        int p = idx / 5, v = idx % 5;
        float s = __ldg(&b2[v]) + part[v * 128 + p] + part[(5 + v) * 128 + p];
        out[(long)(p0 + p) * 5 + v] = s;
    }
}

extern "C" void kernel_launch(void* const* d_in, const int* in_sizes, int n_in,
                              void* d_out, int out_size) {
    const float* x      = (const float*)d_in[0];
    const float* w_spec = (const float*)d_in[1];
    const float* w_skip = (const float*)d_in[2];
    const float* b_skip = (const float*)d_in[3];
    const float* fc0_w  = (const float*)d_in[4];
    const float* fc0_b  = (const float*)d_in[5];
    const float* fc1_w  = (const float*)d_in[6];
    const float* fc1_b  = (const float*)d_in[7];
    const float* fc2_w  = (const float*)d_in[8];
    const float* fc2_b  = (const float*)d_in[9];
    float* out = (float*)d_out;

    float*  ph  = nullptr;  cudaGetSymbolAddress((void**)&ph,  d_h);
    float*  px2 = nullptr;  cudaGetSymbolAddress((void**)&px2, d_x2);
    float2* pS2 = nullptr;  cudaGetSymbolAddress((void**)&pS2, d_S2);
    float2* pS3 = nullptr;  cudaGetSymbolAddress((void**)&pS3, d_S3);
    float2* pG  = nullptr;  cudaGetSymbolAddress((void**)&pG,  d_G);
    float2* pT2 = nullptr;  cudaGetSymbolAddress((void**)&pT2, d_T2);

    static int attr_set = 0;
    if (!attr_set) {
        cudaFuncSetAttribute(k_fc12, cudaFuncAttributeMaxDynamicSharedMemorySize, 66560);
        attr_set = 1;
    }

    // second stream + fork/join events so k_skip overlaps the spectral chain
    cudaStream_t sB;
    cudaStreamCreateWithFlags(&sB, cudaStreamNonBlocking);
    cudaEvent_t evH[4], evS[4];
    for (int l = 0; l < 4; l++) {
        cudaEventCreateWithFlags(&evH[l], cudaEventDisableTiming);
        cudaEventCreateWithFlags(&evS[l], cudaEventDisableTiming);
    }

    k_tw<<<1, 64>>>();
    k_fc0<<<2048, 256>>>(x, fc0_w, fc0_b, ph);
    for (int l = 0; l < 4; l++) {
        // h is ready on stream 0 here; fork skip onto sB
        cudaEventRecord(evH[l], 0);
        cudaStreamWaitEvent(sB, evH[l], 0);
        k_skip<<<1024, 192, 0, sB>>>(ph, w_skip + l * 96 * 96, b_skip + l * 96, px2);
        cudaEventRecord(evS[l], sB);

        // spectral chain on stream 0
        k_fwdZY<<<3072, 256>>>(ph, pS2);
        k_fwdX<<<1536, 128>>>(pS2, pS3);
        k_mix<<<768, 128>>>(pS3, w_spec + (long)l * 4 * 96 * 96 * 1024, pG);
        k_invX<<<1536, 256>>>(pG, pT2);

        // join: invYZ needs both T2 (stream 0) and x2 (sB)
        cudaStreamWaitEvent(0, evS[l], 0);
        k_invYZ<<<6144, 256>>>(pT2, px2, ph, (l < 3) ? 1 : 0);
    }
    k_fc12<<<1024, 256, 66560>>>(ph, fc1_w, fc1_b, fc2_w, fc2_b, out);
}

// round 17
// speedup vs baseline: 1.0840x; 1.0840x over previous
#include <cuda_runtime.h>
#include <math.h>

#define NP 131072   // 64*64*32 voxels
#define CH 96

// ---- scratch (static device arrays; no allocation allowed) ----
__device__ float  d_h [CH*NP];          // [c][x][y][z]
__device__ float  d_x2[CH*NP];          // skip-conv output
__device__ float2 d_S2[CH*64*16*8];     // after z+y DFT [c][x][ky][kz]
__device__ float2 d_S3[CH*16*16*8];     // after x-DFT   [c][kx][ky][kz]
__device__ float2 d_G [CH*16*16*8];     // mode-mixed, i-half 0  [o][kx][ky][kz]
__device__ float2 d_G2[CH*16*16*8];     // mode-mixed, i-half 1
__device__ float2 d_T2[CH*64*16*8];     // inv x         [o][x][ky][kz]
__device__ float2 d_tw[64];             // e^{-2pi i r/64}

__global__ void k_tw() {
    int t = threadIdx.x;
    float s, c;
    sincospif(t * (2.0f / 64.0f), &s, &c);
    d_tw[t] = make_float2(c, -s);       // e^{-2*pi*i*t/64}
}

// ---- tf32 helpers ----
__device__ __forceinline__ unsigned f2tf(float f) {
    unsigned r;
    asm("cvt.rna.tf32.f32 %0, %1;" : "=r"(r) : "f"(f));
    return r;
}
__device__ __forceinline__ void mma_tf32(float* c, const unsigned* a, const unsigned* b) {
    asm("mma.sync.aligned.m16n8k8.row.col.f32.tf32.tf32.f32 "
        "{%0,%1,%2,%3}, {%4,%5,%6,%7}, {%8,%9}, {%0,%1,%2,%3};"
        : "+f"(c[0]), "+f"(c[1]), "+f"(c[2]), "+f"(c[3])
        : "r"(a[0]), "r"(a[1]), "r"(a[2]), "r"(a[3]), "r"(b[0]), "r"(b[1]));
}
__device__ __forceinline__ float2 cmul(float2 a, float2 b) {
    return make_float2(a.x * b.x - a.y * b.y, a.x * b.y + a.y * b.x);
}

// ---- fc0: [p][nt][nvar] + grid -> h[c][p] ----
__global__ void k_fc0(const float* __restrict__ x, const float* __restrict__ w,
                      const float* __restrict__ b, float* __restrict__ h) {
    __shared__ float vsh[64 * 29];
    __shared__ float wsh[28 * 96];
    __shared__ float bsh[96];
    int t = threadIdx.x;                 // 256
    int p0 = blockIdx.x * 64;
    for (int idx = t; idx < 64 * 25; idx += 256) {
        int p = idx / 25, j = idx % 25;
        int nv = j / 5, nt = j % 5;      // v[nv*5+nt] = x[p,nt,nv]
        vsh[p * 29 + j] = x[(p0 + p) * 25 + nt * 5 + nv];
    }
    if (t < 192) {
        int p = t % 64, j = t / 64;
        int pg = p0 + p;
        float g;
        if (j == 0)      g = (float)(pg >> 11)        * (1.0f / 63.0f);
        else if (j == 1) g = (float)((pg >> 5) & 63)  * (1.0f / 63.0f);
        else             g = (float)(pg & 31)         * (1.0f / 31.0f);
        vsh[p * 29 + 25 + j] = g;
    }
    for (int idx = t; idx < 28 * 96; idx += 256) wsh[idx] = w[idx];
    if (t < 96) bsh[t] = b[t];
    __syncthreads();
    int p = t & 63;
    for (int c = t >> 6; c < 96; c += 4) {
        float acc = bsh[c];
        #pragma unroll
        for (int j = 0; j < 28; j++) acc = fmaf(vsh[p * 29 + j], wsh[j * 96 + c], acc);
        h[c * NP + p0 + p] = acc;
    }
}

// ---- fused forward z-DFT + y-DFT: h[c][x][y][z] -> S2[c][x][ky<16][kz<8] ----
__global__ void __launch_bounds__(256, 5)
k_fwdZY(const float* __restrict__ h, float2* __restrict__ S2) {
    __shared__ float  sh[2 * 64 * 33];   // [cxi][y][z] padded
    __shared__ float2 s1[2 * 64 * 9];    // [cxi][y][kz] padded
    __shared__ float2 tws[64];
    __shared__ float2 ttab[128];         // [grp][z][kzi]: tw for kz = grp+2*kzi
    int t = threadIdx.x;                 // 256
    const float4* row4 = (const float4*)(h + (long)blockIdx.x * 4096);
    #pragma unroll
    for (int fi = t; fi < 1024; fi += 256) {
        float4 v = row4[fi];
        int cxi = fi >> 9, rem = fi & 511;
        int y = rem >> 3, z = (rem & 7) * 4;
        float* dst = sh + cxi * 2112 + y * 33 + z;
        dst[0] = v.x; dst[1] = v.y; dst[2] = v.z; dst[3] = v.w;
    }
    if (t < 64) tws[t] = d_tw[t];
    if (t >= 64 && t < 192) {
        int e = t - 64;                  // grp = e>>6, z = (e>>2)&15, kzi = e&3
        int grp = e >> 6, z = (e >> 2) & 15, kzi = e & 3;
        ttab[e] = d_tw[(2 * (grp + 2 * kzi) * z) & 63];
    }
    __syncthreads();
    // phase 1: z-DFT. thread = (cxi, grp, y): kz = {grp, grp+2, grp+4, grp+6}
    {
        int cxi = t >> 7, u = t & 127;
        int grp = u >> 6, y = u & 63;
        float sgn = grp ? -1.f : 1.f;    // (-1)^kz, kz parity = grp
        const float* shy = sh + cxi * 2112 + y * 33;
        const float4* tt = (const float4*)(ttab + grp * 64);
        float r0 = 0.f, i0 = 0.f, r1 = 0.f, i1 = 0.f;
        float r2 = 0.f, i2 = 0.f, r3 = 0.f, i3 = 0.f;
        #pragma unroll
        for (int z = 0; z < 16; z++) {
            float s = fmaf(sgn, shy[z + 16], shy[z]);
            float4 wa = tt[z * 2 + 0];   // kz = grp, grp+2
            float4 wb = tt[z * 2 + 1];   // kz = grp+4, grp+6
            r0 = fmaf(s, wa.x, r0); i0 = fmaf(s, wa.y, i0);
            r1 = fmaf(s, wa.z, r1); i1 = fmaf(s, wa.w, i1);
            r2 = fmaf(s, wb.x, r2); i2 = fmaf(s, wb.y, i2);
            r3 = fmaf(s, wb.z, r3); i3 = fmaf(s, wb.w, i3);
        }
        float2* s1y = s1 + cxi * 576 + y * 9;
        s1y[grp + 0] = make_float2(r0, i0);
        s1y[grp + 2] = make_float2(r1, i1);
        s1y[grp + 4] = make_float2(r2, i2);
        s1y[grp + 6] = make_float2(r3, i3);
    }
    __syncthreads();
    // phase 2: y-DFT. thread = (yq=t&3, kyg=(t>>2)&3, kz=(t>>4)&7, cxi=t>>7)
    {
        int yq = t & 3, kyg = (t >> 2) & 3, kz = (t >> 4) & 7, cxi = t >> 7;
        float sgn2 = (kyg & 1) ? -1.f : 1.f;   // (-1)^kye
        int kye0 = kyg, kye1 = kyg + 4, kye2 = kyg + 56, kye3 = kyg + 60;
        int y0 = yq * 8;
        float2 tw0 = tws[(kye0 * y0) & 63], st0 = tws[kye0];
        float2 tw1 = tws[(kye1 * y0) & 63], st1 = tws[kye1];
        float2 tw2 = tws[(kye2 * y0) & 63], st2 = tws[kye2];
        float2 tw3 = tws[(kye3 * y0) & 63], st3 = tws[kye3];
        float2 a0 = make_float2(0.f, 0.f), a1 = a0, a2 = a0, a3 = a0;
        const float2* s1c = s1 + cxi * 576;
        #pragma unroll
        for (int i = 0; i < 8; i++) {
            int y = y0 + i;
            float2 va = s1c[y * 9 + kz];
            float2 vb = s1c[(y + 32) * 9 + kz];
            float2 fs = make_float2(fmaf(sgn2, vb.x, va.x), fmaf(sgn2, vb.y, va.y));
            a0.x += fs.x * tw0.x - fs.y * tw0.y; a0.y += fs.x * tw0.y + fs.y * tw0.x;
            a1.x += fs.x * tw1.x - fs.y * tw1.y; a1.y += fs.x * tw1.y + fs.y * tw1.x;
            a2.x += fs.x * tw2.x - fs.y * tw2.y; a2.y += fs.x * tw2.y + fs.y * tw2.x;
            a3.x += fs.x * tw3.x - fs.y * tw3.y; a3.y += fs.x * tw3.y + fs.y * tw3.x;
            tw0 = cmul(tw0, st0); tw1 = cmul(tw1, st1);
            tw2 = cmul(tw2, st2); tw3 = cmul(tw3, st3);
        }
        #pragma unroll
        for (int m = 1; m <= 2; m <<= 1) {
            a0.x += __shfl_xor_sync(0xffffffffu, a0.x, m);
            a0.y += __shfl_xor_sync(0xffffffffu, a0.y, m);
            a1.x += __shfl_xor_sync(0xffffffffu, a1.x, m);
            a1.y += __shfl_xor_sync(0xffffffffu, a1.y, m);
            a2.x += __shfl_xor_sync(0xffffffffu, a2.x, m);
            a2.y += __shfl_xor_sync(0xffffffffu, a2.y, m);
            a3.x += __shfl_xor_sync(0xffffffffu, a3.x, m);
            a3.y += __shfl_xor_sync(0xffffffffu, a3.y, m);
        }
        if (yq == 0) {
            long cx = (long)blockIdx.x * 2 + cxi;
            float2* out = S2 + cx * 128;
            out[(kyg + 0)  * 8 + kz] = a0;
            out[(kyg + 4)  * 8 + kz] = a1;
            out[(kyg + 8)  * 8 + kz] = a2;
            out[(kyg + 12) * 8 + kz] = a3;
        }
    }
}

// ---- forward x-DFT (16 kept kx); block = (c, ky), contiguous 64B accesses ----
__global__ void k_fwdX(const float2* __restrict__ S2, float2* __restrict__ S3) {
    __shared__ float2 sh[64 * 8];        // [x][kz]
    __shared__ float2 tws[64];
    int t = threadIdx.x;                 // 128
    int c = blockIdx.x >> 4, ky = blockIdx.x & 15;
    const float2* base = S2 + ((long)c * 1024 + ky) * 8;   // + x*128 + kz
    #pragma unroll
    for (int idx = t; idx < 512; idx += 128) {
        int x = idx >> 3, kz = idx & 7;
        sh[idx] = base[x * 128 + kz];
    }
    if (t < 64) tws[t] = d_tw[t];
    __syncthreads();
    int kx = t >> 3, kz = t & 7;
    int kxe = (kx < 8) ? kx : kx + 48;
    float re = 0.f, im = 0.f;
    #pragma unroll
    for (int x = 0; x < 64; x++) {
        float2 v = sh[x * 8 + kz];
        float2 w = tws[(kxe * x) & 63];
        re += v.x * w.x - v.y * w.y;
        im += v.x * w.y + v.y * w.x;
    }
    S3[(((long)c * 16 + kx) * 16 + ky) * 8 + kz] = make_float2(re, im);
}

// ---- mode mix: zero-smem streaming, i-split over 2 blocks for 2x MLP ----
// block = (corner, o, m-half, i-half): 1536 x 128 thr. Partial sums go to
// G (i-half 0) / G2 (i-half 1); k_invX adds them at load.
__global__ void __launch_bounds__(128)
k_mix(const float2* __restrict__ S3, const float* __restrict__ wspec,
      float2* __restrict__ G, float2* __restrict__ G2) {
    int t = threadIdx.x;                 // 128
    int bid = blockIdx.x;
    int ih = bid & 1;
    int rest = bid >> 1;
    int mh = rest & 1;
    int o = (rest >> 1) % 96;
    int corner = (rest >> 1) / 96;
    int kx0 = (corner & 1) * 8, ky0 = (corner >> 1) * 8;
    int gm0 = mh * 256 + 2 * t;          // even -> float4-aligned S3 pair
    int a = gm0 >> 6, rem = gm0 & 63;
    const float4* S34 = (const float4*)S3;
    long sbase = ((long)(kx0 + a) * 64) + ky0 * 4 + (rem >> 1);   // float4 units
    const float4* w4 = (const float4*)wspec;
    long wbase = (((long)corner * 96) * 96 + o) * 256 + mh * 128 + t;
    int i0 = ih * 48;
    sbase += (long)i0 * 1024;
    wbase += (long)i0 * 24576;
    float2 acc0 = make_float2(0.f, 0.f), acc1 = make_float2(0.f, 0.f);
    #pragma unroll 8
    for (int i = 0; i < 48; i++) {
        float4 s = __ldg(&S34[sbase + (long)i * 1024]);           // (m0.re,m0.im,m1.re,m1.im)
        float4 w = __ldcs(&w4[wbase + (long)i * 24576]);          // 96*256 float4 per i
        acc0.x += s.x * w.x - s.y * w.y;
        acc0.y += s.x * w.y + s.y * w.x;
        acc1.x += s.z * w.z - s.w * w.w;
        acc1.y += s.z * w.w + s.w * w.z;
    }
    int bb = (gm0 >> 3) & 7, kzz = gm0 & 7;
    float4* dst = (float4*)(ih ? G2 : G);
    dst[(((long)o * 16 + kx0 + a) * 16 + ky0 + bb) * 4 + (kzz >> 1)] =
        make_float4(acc0.x, acc0.y, acc1.x, acc1.y);
}

// ---- inverse x (e^{+i}); block = (o, ky); sums the two G halves at load ----
__global__ void k_invX(const float2* __restrict__ G, const float2* __restrict__ G2,
                       float2* __restrict__ T2) {
    __shared__ float2 gsh[128];          // [kx][kz]
    __shared__ float2 tws[64];
    int t = threadIdx.x;                 // 256
    int o = blockIdx.x >> 4, ky = blockIdx.x & 15;
    if (t < 128) {
        int kx = t >> 3, kz = t & 7;
        long gi = (long)o * 2048 + kx * 128 + ky * 8 + kz;
        float2 ga = G[gi], gb = G2[gi];
        gsh[t] = make_float2(ga.x + gb.x, ga.y + gb.y);
    }
    if (t >= 128 && t < 192) tws[t - 128] = d_tw[t - 128];
    __syncthreads();
    int kz = t & 7, x0 = t >> 3;         // x0 0..31
    #pragma unroll
    for (int pp = 0; pp < 2; pp++) {
        int x = x0 + 32 * pp;
        float re = 0.f, im = 0.f;
        #pragma unroll
        for (int kx = 0; kx < 16; kx++) {
            int kxe = (kx < 8) ? kx : kx + 48;
            float2 v = gsh[kx * 8 + kz];
            float2 w = tws[(kxe * x) & 63];     // conj -> e^{+i}
            re += v.x * w.x + v.y * w.y;
            im += v.y * w.x - v.x * w.y;
        }
        T2[(((long)o * 64 + x) * 16 + ky) * 8 + kz] = make_float2(re, im);
    }
}

// ---- skip 1x1 conv via tf32 warp-MMA: x2[o][p] = sum_i W[o][i] h[i][p] + b[o]
// block: 192 threads (6 warps), tile 96o x 128p, K=96 (12 ksteps)
__global__ void k_skip(const float* __restrict__ h, const float* __restrict__ W,
                       const float* __restrict__ b, float* __restrict__ x2) {
    __shared__ unsigned hsh[96 * 128];   // tf32 bits, idx(i,p) = i*128 + (p ^ ((i&3)<<3))
    int t = threadIdx.x;
    int warp = t >> 5, lane = t & 31;
    int q = lane >> 2, r = lane & 3;
    int p0 = blockIdx.x * 128;
    for (int idx = t; idx < 96 * 32; idx += 192) {
        int i = idx >> 5, p = (idx & 31) * 4;
        float4 v = *(const float4*)(h + (long)i * NP + p0 + p);
        int sp = p ^ ((i & 3) << 3);
        uint4 u = make_uint4(f2tf(v.x), f2tf(v.y), f2tf(v.z), f2tf(v.w));
        *(uint4*)(hsh + i * 128 + sp) = u;
    }
    int o0 = warp * 16;
    unsigned A[12][4];
    #pragma unroll
    for (int ks = 0; ks < 12; ks++) {
        A[ks][0] = f2tf(__ldg(&W[(o0 + q) * 96 + ks * 8 + r]));
        A[ks][1] = f2tf(__ldg(&W[(o0 + q + 8) * 96 + ks * 8 + r]));
        A[ks][2] = f2tf(__ldg(&W[(o0 + q) * 96 + ks * 8 + r + 4]));
        A[ks][3] = f2tf(__ldg(&W[(o0 + q + 8) * 96 + ks * 8 + r + 4]));
    }
    float acc[16][4];
    #pragma unroll
    for (int nt = 0; nt < 16; nt++)
        #pragma unroll
        for (int k = 0; k < 4; k++) acc[nt][k] = 0.f;
    __syncthreads();
    #pragma unroll
    for (int ks = 0; ks < 12; ks++) {
        #pragma unroll
        for (int nt = 0; nt < 16; nt++) {
            unsigned bf[2];
            int col = (nt * 8 + q) ^ (r << 3);
            bf[0] = hsh[(ks * 8 + r) * 128 + col];
            bf[1] = hsh[(ks * 8 + r + 4) * 128 + col];
            mma_tf32(acc[nt], A[ks], bf);
        }
    }
    float bv0 = __ldg(&b[o0 + q]);
    float bv8 = __ldg(&b[o0 + q + 8]);
    #pragma unroll
    for (int nt = 0; nt < 16; nt++) {
        int p = p0 + nt * 8 + 2 * r;
        *(float2*)(x2 + (long)(o0 + q) * NP + p)     = make_float2(acc[nt][0] + bv0, acc[nt][1] + bv0);
        *(float2*)(x2 + (long)(o0 + q + 8) * NP + p) = make_float2(acc[nt][2] + bv8, acc[nt][3] + bv8);
    }
}

// ---- fused inverse y + inverse z + skip add + (gelu): writes h in place ----
__global__ void __launch_bounds__(256, 5)
k_invYZ(const float2* __restrict__ T2, const float* __restrict__ x2,
        float* __restrict__ h, int do_gelu) {
    __shared__ float2 t2s[128];          // [ky][kz]
    __shared__ float2 t1s[64 * 9];       // [y][kz] padded
    __shared__ float2 tws[64];
    int t = threadIdx.x;                 // 256
    int ox = blockIdx.x;
    if (t < 128) t2s[t] = T2[(long)ox * 128 + t];
    if (t >= 128 && t < 192) tws[t - 128] = d_tw[t - 128];
    __syncthreads();
    // phase 1: inverse y with twiddle recurrence + y-sign trick.
    {
        int kz = t & 7, yq = t >> 3;     // yq 0..31
        float2 step = tws[yq];           // w(yq)
        float2 tw = make_float2(1.f, 0.f);
        float r1 = 0.f, i1 = 0.f, r2 = 0.f, i2 = 0.f;
        #pragma unroll
        for (int ky = 0; ky < 16; ky++) {
            if (ky == 8) tw = tws[(56 * yq) & 63];   // kye jumps 7 -> 56
            float2 v = t2s[ky * 8 + kz];
            float tr = v.x * tw.x + v.y * tw.y;      // Re(v e^{+i})
            float ti = v.y * tw.x - v.x * tw.y;
            r1 += tr; i1 += ti;
            if (ky & 1) { r2 -= tr; i2 -= ti; }
            else        { r2 += tr; i2 += ti; }
            tw = cmul(tw, step);
        }
        float sc = (kz == 0) ? (1.0f / 131072.0f) : (2.0f / 131072.0f);
        t1s[yq * 9 + kz] = make_float2(r1 * sc, i1 * sc);
        t1s[(yq + 32) * 9 + kz] = make_float2(r2 * sc, i2 * sc);
    }
    __syncthreads();
    // phase 2: inverse z (real part) + skip + gelu; z-symmetry pair (z0, z0+16)
    int z0 = t & 15, yg = t >> 4;        // yg 0..15
    float2 tzs[8];
    {
        float2 st = tws[(2 * z0) & 63];
        tzs[0] = make_float2(1.f, 0.f);
        tzs[1] = st;
        #pragma unroll
        for (int k = 2; k < 8; k++) tzs[k] = cmul(tzs[k - 1], st);
    }
    const float* x2row = x2 + (long)ox * 2048;
    float* hrow = h + (long)ox * 2048;
    #pragma unroll
    for (int pass = 0; pass < 4; pass++) {
        int y = yg + 16 * pass;
        float a = 0.f, bq = 0.f;
        #pragma unroll
        for (int kz = 0; kz < 8; kz++) {
            float2 v = t1s[y * 9 + kz];
            float term = v.x * tzs[kz].x + v.y * tzs[kz].y;  // Re(v e^{+i th})
            a += term;
            if (kz & 1) bq -= term; else bq += term;
        }
        float r1 = a  + x2row[y * 32 + z0];
        float r2 = bq + x2row[y * 32 + z0 + 16];
        if (do_gelu) {
            r1 = 0.5f * r1 * (1.0f + erff(r1 * 0.70710678118f));
            r2 = 0.5f * r2 * (1.0f + erff(r2 * 0.70710678118f));
        }
        hrow[y * 32 + z0]      = r1;
        hrow[y * 32 + z0 + 16] = r2;
    }
}

// ---- fused head: out = gelu(h @ fc1 + b1) @ fc2 + b2 (no d_g round-trip)
__global__ void k_fc12(const float* __restrict__ h, const float* __restrict__ w1,
                       const float* __restrict__ b1, const float* __restrict__ w2,
                       const float* __restrict__ b2, float* __restrict__ out) {
    __shared__ unsigned hsh[96 * 128];   // tf32 bits, idx(i,p) = i*128 + (p ^ ((i&3)<<3))
    __shared__ float w2s[128 * 5];
    __shared__ float part[2 * 5 * 128];  // fc2 partials [half][v][p]
    extern __shared__ float gsh[];       // [j][p] stride 130 -> 66560 B
    int t = threadIdx.x;
    int warp = t >> 5, lane = t & 31;
    int q = lane >> 2, r = lane & 3;
    int p0 = blockIdx.x * 128;
    for (int idx = t; idx < 96 * 32; idx += 256) {
        int i = idx >> 5, p = (idx & 31) * 4;
        float4 v = *(const float4*)(h + (long)i * NP + p0 + p);
        int sp = p ^ ((i & 3) << 3);
        uint4 u = make_uint4(f2tf(v.x), f2tf(v.y), f2tf(v.z), f2tf(v.w));
        *(uint4*)(hsh + i * 128 + sp) = u;
    }
    for (int idx = t; idx < 640; idx += 256) w2s[idx] = w2[idx];
    int j0 = warp * 16;
    unsigned A[12][4];
    #pragma unroll
    for (int ks = 0; ks < 12; ks++) {
        A[ks][0] = f2tf(__ldg(&w1[(ks * 8 + r) * 128 + j0 + q]));
        A[ks][1] = f2tf(__ldg(&w1[(ks * 8 + r) * 128 + j0 + q + 8]));
        A[ks][2] = f2tf(__ldg(&w1[(ks * 8 + r + 4) * 128 + j0 + q]));
        A[ks][3] = f2tf(__ldg(&w1[(ks * 8 + r + 4) * 128 + j0 + q + 8]));
    }
    float acc[16][4];
    #pragma unroll
    for (int nt = 0; nt < 16; nt++)
        #pragma unroll
        for (int k = 0; k < 4; k++) acc[nt][k] = 0.f;
    __syncthreads();
    #pragma unroll
    for (int ks = 0; ks < 12; ks++) {
        #pragma unroll
        for (int nt = 0; nt < 16; nt++) {
            unsigned bf[2];
            int col = (nt * 8 + q) ^ (r << 3);
            bf[0] = hsh[(ks * 8 + r) * 128 + col];
            bf[1] = hsh[(ks * 8 + r + 4) * 128 + col];
            mma_tf32(acc[nt], A[ks], bf);
        }
    }
    float bj0 = __ldg(&b1[j0 + q]);
    float bj8 = __ldg(&b1[j0 + q + 8]);
    #pragma unroll
    for (int nt = 0; nt < 16; nt++) {
        int p = nt * 8 + 2 * r;
        float s0 = acc[nt][0] + bj0, s1 = acc[nt][1] + bj0;
        float s2 = acc[nt][2] + bj8, s3 = acc[nt][3] + bj8;
        s0 = 0.5f * s0 * (1.0f + erff(s0 * 0.70710678118f));
        s1 = 0.5f * s1 * (1.0f + erff(s1 * 0.70710678118f));
        s2 = 0.5f * s2 * (1.0f + erff(s2 * 0.70710678118f));
        s3 = 0.5f * s3 * (1.0f + erff(s3 * 0.70710678118f));
        *(float2*)(gsh + (j0 + q) * 130 + p)     = make_float2(s0, s1);
        *(float2*)(gsh + (j0 + q + 8) * 130 + p) = make_float2(s2, s3);
    }
    __syncthreads();
    // fc2 stage: thread = (p = t&127, half = t>>7); 64 j each
    {
        int p = t & 127, half = t >> 7;
        float a0 = 0.f, a1 = 0.f, a2 = 0.f, a3 = 0.f, a4 = 0.f;
        int jb = half * 64;
        #pragma unroll 4
        for (int j = jb; j < jb + 64; j++) {
            float gv = gsh[j * 130 + p];
            a0 = fmaf(gv, w2s[j * 5 + 0], a0);
            a1 = fmaf(gv, w2s[j * 5 + 1], a1);
            a2 = fmaf(gv, w2s[j * 5 + 2], a2);
            a3 = fmaf(gv, w2s[j * 5 + 3], a3);
            a4 = fmaf(gv, w2s[j * 5 + 4], a4);
        }
        part[(half * 5 + 0) * 128 + p] = a0;
        part[(half * 5 + 1) * 128 + p] = a1;
        part[(half * 5 + 2) * 128 + p] = a2;
        part[(half * 5 + 3) * 128 + p] = a3;
        part[(half * 5 + 4) * 128 + p] = a4;
    }
    __syncthreads();
    for (int idx = t; idx < 640; idx += 256) {
        int p = idx / 5, v = idx % 5;
        float s = __ldg(&b2[v]) + part[v * 128 + p] + part[(5 + v) * 128 + p];
        out[(long)(p0 + p) * 5 + v] = s;
    }
}

extern "C" void kernel_launch(void* const* d_in, const int* in_sizes, int n_in,
                              void* d_out, int out_size) {
    const float* x      = (const float*)d_in[0];
    const float* w_spec = (const float*)d_in[1];
    const float* w_skip = (const float*)d_in[2];
    const float* b_skip = (const float*)d_in[3];
    const float* fc0_w  = (const float*)d_in[4];
    const float* fc0_b  = (const float*)d_in[5];
    const float* fc1_w  = (const float*)d_in[6];
    const float* fc1_b  = (const float*)d_in[7];
    const float* fc2_w  = (const float*)d_in[8];
    const float* fc2_b  = (const float*)d_in[9];
    float* out = (float*)d_out;

    float*  ph  = nullptr;  cudaGetSymbolAddress((void**)&ph,  d_h);
    float*  px2 = nullptr;  cudaGetSymbolAddress((void**)&px2, d_x2);
    float2* pS2 = nullptr;  cudaGetSymbolAddress((void**)&pS2, d_S2);
    float2* pS3 = nullptr;  cudaGetSymbolAddress((void**)&pS3, d_S3);
    float2* pG  = nullptr;  cudaGetSymbolAddress((void**)&pG,  d_G);
    float2* pG2 = nullptr;  cudaGetSymbolAddress((void**)&pG2, d_G2);
    float2* pT2 = nullptr;  cudaGetSymbolAddress((void**)&pT2, d_T2);

    static int attr_set = 0;
    if (!attr_set) {
        cudaFuncSetAttribute(k_fc12, cudaFuncAttributeMaxDynamicSharedMemorySize, 66560);
        attr_set = 1;
    }

    // second stream + fork/join events so k_skip overlaps the spectral chain
    cudaStream_t sB;
    cudaStreamCreateWithFlags(&sB, cudaStreamNonBlocking);
    cudaEvent_t evH[4], evS[4];
    for (int l = 0; l < 4; l++) {
        cudaEventCreateWithFlags(&evH[l], cudaEventDisableTiming);
        cudaEventCreateWithFlags(&evS[l], cudaEventDisableTiming);
    }

    k_tw<<<1, 64>>>();
    k_fc0<<<2048, 256>>>(x, fc0_w, fc0_b, ph);
    for (int l = 0; l < 4; l++) {
        // h is ready on stream 0 here; fork skip onto sB
        cudaEventRecord(evH[l], 0);
        cudaStreamWaitEvent(sB, evH[l], 0);
        k_skip<<<1024, 192, 0, sB>>>(ph, w_skip + l * 96 * 96, b_skip + l * 96, px2);
        cudaEventRecord(evS[l], sB);

        // spectral chain on stream 0
        k_fwdZY<<<3072, 256>>>(ph, pS2);
        k_fwdX<<<1536, 128>>>(pS2, pS3);
        k_mix<<<1536, 128>>>(pS3, w_spec + (long)l * 4 * 96 * 96 * 1024, pG, pG2);
        k_invX<<<1536, 256>>>(pG, pG2, pT2);

        // join: invYZ needs both T2 (stream 0) and x2 (sB)
        cudaStreamWaitEvent(0, evS[l], 0);
        k_invYZ<<<6144, 256>>>(pT2, px2, ph, (l < 3) ? 1 : 0);
    }
    k_fc12<<<1024, 256, 66560>>>(ph, fc1_w, fc1_b, fc2_w, fc2_b, out);
}